// round 8
// baseline (speedup 1.0000x reference)
#include <cuda_runtime.h>
#include <cuda_bf16.h>

// ---------------------------------------------------------------------------
// MLP_TI_Gram: y = MLP(mean-of-shifted-diagonal of per-batch Gram matrix)
// diag-mean == circular autocorrelation == FFT(sum_d |FFT(x_d)|^2)/N^2
// (Wiener-Khinchin; P real-even so inverse == forward FFT, real part).
// B=128, N=1024, H=128.
// fftcorr: four-step 32x32 FFT with warp-shuffle 32-pt kernels.
// Pipeline: fftcorr -> tiled gemm1 (final h1) -> mlp23.
// ---------------------------------------------------------------------------

#define BATCH 128
#define NSEQ  1024
#define HID   128

typedef unsigned long long u64;

__device__ float g_c[BATCH * NSEQ];    // correlation (scratch)
__device__ float g_h1[BATCH * HID];    // layer-1 activations (scratch)

// ---- f32x2 packed helpers (Blackwell, PTX-only) ---------------------------
__device__ __forceinline__ u64 pk2(float lo, float hi) {
    u64 r;
    asm("mov.b64 %0, {%1,%2};" : "=l"(r) : "f"(lo), "f"(hi));
    return r;
}
__device__ __forceinline__ void upk2(u64 v, float& lo, float& hi) {
    asm("mov.b64 {%0,%1}, %2;" : "=f"(lo), "=f"(hi) : "l"(v));
}
__device__ __forceinline__ u64 fma2(u64 a, u64 b, u64 c) {
    u64 d;
    asm("fma.rn.f32x2 %0, %1, %2, %3;" : "=l"(d) : "l"(a), "l"(b), "l"(c));
    return d;
}
__device__ __forceinline__ u64 add2(u64 a, u64 b) {
    u64 d;
    asm("add.rn.f32x2 %0, %1, %2;" : "=l"(d) : "l"(a), "l"(b));
    return d;
}

__device__ __forceinline__ float celu1(float v) {
    return v > 0.0f ? v : expm1f(v);
}
__device__ __forceinline__ float2 cmul(float2 a, float2 b) {
    return make_float2(a.x * b.x - a.y * b.y, a.x * b.y + a.y * b.x);
}

// padded physical index for stride-32-friendly smem layout
__device__ __forceinline__ int phys(int n) { return n + (n >> 5); }

// ---------------------------------------------------------------------------
// In-warp 32-point FFT (radix-2 DIF), NV interleaved signals, lane = input
// index. Output at lane L is X[bitrev5(L)]. Twiddles from twf (W_1024 table,
// stride 32 => W_32).
// ---------------------------------------------------------------------------
template <int NV>
__device__ __forceinline__ void wfft32(float2* v, int lane,
                                       const float2* __restrict__ twf) {
#pragma unroll
    for (int h = 16; h >= 1; h >>= 1) {
        const bool up = (lane & h) != 0;
        float2 wt = (h > 1) ? twf[(lane & (h - 1)) * (512 / h)]
                            : make_float2(1.0f, 0.0f);
#pragma unroll
        for (int r = 0; r < NV; r++) {
            float px = __shfl_xor_sync(0xffffffffu, v[r].x, h);
            float py = __shfl_xor_sync(0xffffffffu, v[r].y, h);
            if (!up) {
                v[r] = make_float2(v[r].x + px, v[r].y + py);
            } else {
                float2 d = make_float2(px - v[r].x, py - v[r].y);
                v[r] = cmul(d, wt);
            }
        }
    }
}

// ---------------------------------------------------------------------------
// Kernel 1: correlation via FFT (Wiener-Khinchin), four-step 32x32.
// 128 blocks (one per batch), 512 threads (16 warps).
// Forward: 2 complex 1024-pt FFTs (ch0 + i*ch1, ch2 + 0i).
//   X[c+32d] = FFT32_b( W_1024^{bc} * FFT32_a( x[32a+b] )[c] )[d]
// P[k] = 0.5*(|Z01[k]|^2 + |Z01[N-k]|^2) + |Z2[k]|^2
// c[r] = Re(FFT(P))[r] / N^2.
// ---------------------------------------------------------------------------
__global__ __launch_bounds__(512, 1)
void fftcorr_kernel(const float* __restrict__ x) {
    __shared__ float2 sA[2][1056];   // phys-padded complex arrays
    __shared__ float2 sB[2][1056];
    __shared__ float2 twf[1024];     // full W_1024 table

    const int b    = blockIdx.x;
    const int t    = threadIdx.x;
    const int lane = t & 31;
    const int w    = t >> 5;         // 0..15

    // full twiddle table: twf[m] = exp(-2*pi*i*m/1024)
    for (int m = t; m < 1024; m += 512) {
        float s_, c_;
        sincospif(-(float)m * (1.0f / 512.0f), &s_, &c_);
        twf[m] = make_float2(c_, s_);
    }
    // zero imag of channel-2 signal
    sA[1][phys(t)].y = 0.0f;
    sA[1][phys(t + 512)].y = 0.0f;

    // load x[b]: 3072 floats = 768 float4, scatter to (j, d), padded layout
    {
        const float4* __restrict__ xv = (const float4*)(x + (size_t)b * NSEQ * 3);
        for (int i = t; i < 768; i += 512) {
            float4 v = xv[i];
            float vals[4] = {v.x, v.y, v.z, v.w};
            int e = 4 * i;
#pragma unroll
            for (int k = 0; k < 4; k++) {
                int ee = e + k;
                int j = ee / 3;
                int d = ee - 3 * j;
                int pj = phys(j);
                if (d == 0)      sA[0][pj].x = vals[k];
                else if (d == 1) sA[0][pj].y = vals[k];
                else             sA[1][pj].x = vals[k];
            }
        }
    }
    __syncthreads();

    const int cb = __brev(lane) >> 27;   // bitrev5(lane)

    // ---- forward step A: 64 column FFTs over a (4 per warp) + twiddle ----
    {
        float2 v[4];
        int fi[4], bc[4];
#pragma unroll
        for (int r = 0; r < 4; r++) {
            int id = w + 16 * r;             // (0,w),(0,w+16),(1,w),(1,w+16)
            fi[r] = id >> 5;
            bc[r] = id & 31;
            v[r] = sA[fi[r]][33 * lane + bc[r]];   // x[32*lane + bc]
        }
        wfft32<4>(v, lane, twf);
        // lane holds Y[b][c], c = cb; twiddle W_1024^{b*c}, store transposed
#pragma unroll
        for (int r = 0; r < 4; r++) {
            float2 y = cmul(v[r], twf[(bc[r] * cb) & 1023]);
            sB[fi[r]][33 * cb + bc[r]] = y;
        }
    }
    __syncthreads();

    // ---- forward step B: 64 row FFTs over b (4 per warp) -> X in sA ----
    {
        float2 v[4];
        int fi[4], cc[4];
#pragma unroll
        for (int r = 0; r < 4; r++) {
            int id = w + 16 * r;
            fi[r] = id >> 5;
            cc[r] = id & 31;
            v[r] = sB[fi[r]][33 * cc[r] + lane];   // lane = b
        }
        wfft32<4>(v, lane, twf);
        // lane holds X[cc + 32*d], d = cb; phys(cc+32d) = cc + 33*cb
#pragma unroll
        for (int r = 0; r < 4; r++) {
            sA[fi[r]][cc[r] + 33 * cb] = v[r];
        }
    }
    __syncthreads();

    // ---- power spectrum: P + 0i into sB[0] ----
#pragma unroll
    for (int it = 0; it < 2; it++) {
        int k = t + it * 512;
        int m = (1024 - k) & 1023;
        float2 z  = sA[0][phys(k)];
        float2 zm = sA[0][phys(m)];
        float2 z2 = sA[1][phys(k)];
        float P = 0.5f * (z.x * z.x + z.y * z.y + zm.x * zm.x + zm.y * zm.y)
                + (z2.x * z2.x + z2.y * z2.y);
        sB[0][phys(k)] = make_float2(P, 0.0f);
    }
    __syncthreads();

    // ---- inverse (== forward on real-even P), four-step, 1 signal ----
    {
        float2 v[2];
        int bc[2];
#pragma unroll
        for (int r = 0; r < 2; r++) {
            bc[r] = w + 16 * r;
            v[r] = sB[0][33 * lane + bc[r]];
        }
        wfft32<2>(v, lane, twf);
#pragma unroll
        for (int r = 0; r < 2; r++) {
            float2 y = cmul(v[r], twf[(bc[r] * cb) & 1023]);
            sA[0][33 * cb + bc[r]] = y;
        }
    }
    __syncthreads();
    {
        float2 v[2];
        int cc[2];
#pragma unroll
        for (int r = 0; r < 2; r++) {
            cc[r] = w + 16 * r;
            v[r] = sA[0][33 * cc[r] + lane];
        }
        wfft32<2>(v, lane, twf);
        // result index k = cc + 32*d, d = cb; stash real part for coalesced out
        float* cr = (float*)sB[1];
#pragma unroll
        for (int r = 0; r < 2; r++) {
            int k = cc[r] + 32 * cb;
            cr[phys(k)] = v[r].x;
        }
    }
    __syncthreads();

    const float inv = 1.0f / (1024.0f * 1024.0f);
    {
        float* cr = (float*)sB[1];
        g_c[(size_t)b * NSEQ + t]       = cr[phys(t)] * inv;
        g_c[(size_t)b * NSEQ + t + 512] = cr[phys(t + 512)] * inv;
    }
}

// ---------------------------------------------------------------------------
// Kernel 2: tiled layer-1 GEMM, full K per block, writes FINAL h1 (w/ celu).
// Grid 128 = 16 batch-tiles (8 batches) x 8 h-tiles (16 h). 512 threads.
// ---------------------------------------------------------------------------
#define CSH_PITCH 1025
#define RED_PITCH 66
#define GEMM1_SMEM ((4 * CSH_PITCH + 1024 * 16 + 32 * RED_PITCH) * 8)

__global__ __launch_bounds__(512, 1)
void gemm1_kernel(const float* __restrict__ W1, const float* __restrict__ b1) {
    extern __shared__ char dsm[];
    u64 (*csh)[CSH_PITCH] = (u64(*)[CSH_PITCH])dsm;
    u64 (*w1d)[16]        = (u64(*)[16])(dsm + 4 * CSH_PITCH * 8);
    u64 (*red)[RED_PITCH] = (u64(*)[RED_PITCH])(dsm + (4 * CSH_PITCH + 1024 * 16) * 8);

    const int t  = threadIdx.x;
    const int bt = blockIdx.x >> 3;
    const int ht = blockIdx.x & 7;
    const int b0 = bt * 8;
    const int H0 = ht * 16;

#pragma unroll
    for (int it = 0; it < 8; it++) {
        int idx = t + it * 512;
        int bp_ = idx >> 10, j = idx & 1023;
        csh[bp_][j] = pk2(g_c[(b0 + 2 * bp_) * NSEQ + j],
                          g_c[(b0 + 2 * bp_ + 1) * NSEQ + j]);
    }
#pragma unroll
    for (int it = 0; it < 8; it++) {
        int idx = t + it * 512;
        int j = idx >> 2, hq = idx & 3;
        float4 wv = *(const float4*)&W1[j * HID + H0 + hq * 4];
        ulonglong2* dst = (ulonglong2*)&w1d[j][hq * 4];
        dst[0] = make_ulonglong2(pk2(wv.x, wv.x), pk2(wv.y, wv.y));
        dst[1] = make_ulonglong2(pk2(wv.z, wv.z), pk2(wv.w, wv.w));
    }
    __syncthreads();

    const int bp = t & 3;
    const int h4 = (t >> 2) & 3;
    const int jq = t >> 4;
    const int j0 = jq * 32;

    u64 a0 = 0ull, a1 = 0ull, a2 = 0ull, a3 = 0ull;
#pragma unroll 8
    for (int j = j0; j < j0 + 32; j++) {
        u64 cv = csh[bp][j];
        const ulonglong2* wr = (const ulonglong2*)&w1d[j][h4 * 4];
        ulonglong2 w01 = wr[0];
        ulonglong2 w23 = wr[1];
        a0 = fma2(cv, w01.x, a0);
        a1 = fma2(cv, w01.y, a1);
        a2 = fma2(cv, w23.x, a2);
        a3 = fma2(cv, w23.y, a3);
    }
    {
        ulonglong2* rr = (ulonglong2*)&red[jq][bp * 16 + h4 * 4];
        rr[0] = make_ulonglong2(a0, a1);
        rr[1] = make_ulonglong2(a2, a3);
    }
    __syncthreads();

    if (t < 64) {
        int bp_ = t >> 4, h = t & 15;
        int cell = bp_ * 16 + h;
        u64 s0 = 0ull, s1 = 0ull, s2 = 0ull, s3 = 0ull;
#pragma unroll
        for (int q = 0; q < 32; q += 4) {
            s0 = add2(s0, red[q + 0][cell]);
            s1 = add2(s1, red[q + 1][cell]);
            s2 = add2(s2, red[q + 2][cell]);
            s3 = add2(s3, red[q + 3][cell]);
        }
        u64 s = add2(add2(s0, s1), add2(s2, s3));
        float va, vb;
        upk2(s, va, vb);
        float bb = b1[H0 + h];
        g_h1[(b0 + 2 * bp_) * HID + H0 + h]     = celu1(va + bb);
        g_h1[(b0 + 2 * bp_ + 1) * HID + H0 + h] = celu1(vb + bb);
    }
}

// ---------------------------------------------------------------------------
// Kernel 3: layers 2+3. 128 blocks (one per batch), 256 threads (k split 2).
// ---------------------------------------------------------------------------
__global__ __launch_bounds__(256, 1)
void mlp23_kernel(const float* __restrict__ W2, const float* __restrict__ b2,
                  const float* __restrict__ W3, const float* __restrict__ b3,
                  float* __restrict__ out) {
    __shared__ float h1s[HID];
    __shared__ float s2[2][HID];

    const int b = blockIdx.x, t = threadIdx.x;
    if (t < HID) h1s[t] = g_h1[b * HID + t];
    __syncthreads();

    const int kh = t >> 7, h = t & (HID - 1);
    const int k0 = kh * 64;
    float acc0 = 0.f, acc1 = 0.f, acc2 = 0.f, acc3 = 0.f;
#pragma unroll
    for (int k = k0; k < k0 + 64; k += 4) {
        acc0 += h1s[k + 0] * W2[(k + 0) * HID + h];
        acc1 += h1s[k + 1] * W2[(k + 1) * HID + h];
        acc2 += h1s[k + 2] * W2[(k + 2) * HID + h];
        acc3 += h1s[k + 3] * W2[(k + 3) * HID + h];
    }
    s2[kh][h] = (acc0 + acc1) + (acc2 + acc3);
    __syncthreads();

    if (t < HID) {
        float v = s2[0][t] + s2[1][t] + b2[t];
        s2[0][t] = celu1(v) * W3[t];
    }
    __syncthreads();
#pragma unroll
    for (int o = 64; o > 0; o >>= 1) {
        if (t < o) s2[0][t] += s2[0][t + o];
        __syncthreads();
    }
    if (t == 0) out[b] = s2[0][0] + b3[0];
}

// ---------------------------------------------------------------------------
extern "C" void kernel_launch(void* const* d_in, const int* in_sizes, int n_in,
                              void* d_out, int out_size) {
    const float* x  = (const float*)d_in[0];
    const float* W1 = (const float*)d_in[1];
    const float* b1 = (const float*)d_in[2];
    const float* W2 = (const float*)d_in[3];
    const float* b2 = (const float*)d_in[4];
    const float* W3 = (const float*)d_in[5];
    const float* b3 = (const float*)d_in[6];
    float* out = (float*)d_out;

    cudaFuncSetAttribute(gemm1_kernel,
                         cudaFuncAttributeMaxDynamicSharedMemorySize, GEMM1_SMEM);

    fftcorr_kernel<<<BATCH, 512>>>(x);
    gemm1_kernel<<<128, 512, GEMM1_SMEM>>>(W1, b1);
    mlp23_kernel<<<BATCH, 256>>>(W2, b2, W3, b3, out);
}

// round 9
// speedup vs baseline: 1.1004x; 1.1004x over previous
#include <cuda_runtime.h>
#include <cuda_bf16.h>

// ---------------------------------------------------------------------------
// MLP_TI_Gram: y = MLP(mean-of-shifted-diagonal of per-batch Gram matrix)
// diag-mean == circular autocorrelation == FFT(sum_d |FFT(x_d)|^2)/N^2
// (Wiener-Khinchin; P real-even so inverse == forward FFT, real part).
// B=128, N=1024, H=128.
// Pipeline: fftcorr (radix-4, XOR-swizzled smem) -> fused gemm1+mlp23.
// ---------------------------------------------------------------------------

#define BATCH 128
#define NSEQ  1024
#define HID   128

typedef unsigned long long u64;

__device__ float    g_c[BATCH * NSEQ];   // correlation (scratch)
__device__ float    g_h1[BATCH * HID];   // layer-1 activations (scratch)
__device__ unsigned g_flag2[16];         // per-btile h1-done (monotonic)

// ---- f32x2 packed helpers (Blackwell, PTX-only) ---------------------------
__device__ __forceinline__ u64 pk2(float lo, float hi) {
    u64 r;
    asm("mov.b64 %0, {%1,%2};" : "=l"(r) : "f"(lo), "f"(hi));
    return r;
}
__device__ __forceinline__ void upk2(u64 v, float& lo, float& hi) {
    asm("mov.b64 {%0,%1}, %2;" : "=f"(lo), "=f"(hi) : "l"(v));
}
__device__ __forceinline__ u64 fma2(u64 a, u64 b, u64 c) {
    u64 d;
    asm("fma.rn.f32x2 %0, %1, %2, %3;" : "=l"(d) : "l"(a), "l"(b), "l"(c));
    return d;
}
__device__ __forceinline__ u64 add2(u64 a, u64 b) {
    u64 d;
    asm("add.rn.f32x2 %0, %1, %2;" : "=l"(d) : "l"(a), "l"(b));
    return d;
}

__device__ __forceinline__ float celu1(float v) {
    return v > 0.0f ? v : expm1f(v);
}
__device__ __forceinline__ float2 cmul(float2 a, float2 b) {
    return make_float2(a.x * b.x - a.y * b.y, a.x * b.y + a.y * b.x);
}
// XOR bank swizzle: bijection on [0,1024); keeps linear runs conflict-free and
// makes the stage-0 stride-4 scatter hit all 32 banks.
__device__ __forceinline__ int swz(int a) { return a ^ ((a >> 5) & 31); }

__device__ __forceinline__ unsigned ldacq(const unsigned* p) {
    unsigned v;
    asm volatile("ld.acquire.gpu.u32 %0, [%1];" : "=r"(v) : "l"(p));
    return v;
}

// ---------------------------------------------------------------------------
// Kernel 1: correlation via FFT (Wiener-Khinchin), radix-4 Stockham,
// XOR-swizzled shared memory. 128 blocks (one per batch), 512 threads.
// ---------------------------------------------------------------------------
__global__ __launch_bounds__(512, 1)
void fftcorr_kernel(const float* __restrict__ x) {
    __shared__ float2 bufA[2][1024];   // 16KB (swizzled layout)
    __shared__ float2 bufB[2][1024];   // 16KB (swizzled layout)
    __shared__ float2 tw[512];         // W_1024^m, m in [0,512)

    const int b = blockIdx.x;
    const int t = threadIdx.x;

    // twiddle: tw[m] = exp(-2*pi*i*m/1024)
    {
        float s_, c_;
        sincospif(-(float)t * (1.0f / 512.0f), &s_, &c_);
        tw[t] = make_float2(c_, s_);
    }
    // zero imag of channel-2 signal (bijection: linear covers all slots)
    bufA[1][t].y = 0.0f;
    bufA[1][t + 512].y = 0.0f;

    // load x[b]: 3072 floats = 768 float4, scatter to (j, d), swizzled
    {
        const float4* __restrict__ xv = (const float4*)(x + (size_t)b * NSEQ * 3);
        for (int i = t; i < 768; i += 512) {
            float4 v = xv[i];
            float vals[4] = {v.x, v.y, v.z, v.w};
            int e = 4 * i;
#pragma unroll
            for (int k = 0; k < 4; k++) {
                int ee = e + k;
                int j = ee / 3;
                int d = ee - 3 * j;
                int pj = swz(j);
                if (d == 0)      bufA[0][pj].x = vals[k];
                else if (d == 1) bufA[0][pj].y = vals[k];
                else             bufA[1][pj].x = vals[k];
            }
        }
    }
    __syncthreads();

    const int f = t >> 8;     // signal (0: ch0+i*ch1, 1: ch2)
    const int i = t & 255;

    // ---- forward: 5 radix-4 stages, 2 signals ----
    {
        float2 (*src)[1024] = bufA;
        float2 (*dst)[1024] = bufB;
#pragma unroll
        for (int s = 0; s < 5; s++) {
            const int L = 1 << (2 * s);
            const int q = i & (L - 1);
            const int d = ((i >> (2 * s)) << (2 * s + 2)) | q;
            const float2 w1t = tw[q << (8 - 2 * s)];
            const float2 w2t = make_float2(w1t.x * w1t.x - w1t.y * w1t.y,
                                           2.0f * w1t.x * w1t.y);
            const float2 w3t = cmul(w2t, w1t);

            float2 a0 = src[f][swz(i)];
            float2 a1 = src[f][swz(i + 256)];
            float2 a2 = src[f][swz(i + 512)];
            float2 a3 = src[f][swz(i + 768)];
            float2 b1 = cmul(a1, w1t);
            float2 b2 = cmul(a2, w2t);
            float2 b3 = cmul(a3, w3t);

            float2 t02p = make_float2(a0.x + b2.x, a0.y + b2.y);
            float2 t02m = make_float2(a0.x - b2.x, a0.y - b2.y);
            float2 t13p = make_float2(b1.x + b3.x, b1.y + b3.y);
            float2 t13m = make_float2(b1.x - b3.x, b1.y - b3.y);

            dst[f][swz(d)]         = make_float2(t02p.x + t13p.x, t02p.y + t13p.y);
            dst[f][swz(d + L)]     = make_float2(t02m.x + t13m.y, t02m.y - t13m.x);
            dst[f][swz(d + 2 * L)] = make_float2(t02p.x - t13p.x, t02p.y - t13p.y);
            dst[f][swz(d + 3 * L)] = make_float2(t02m.x - t13m.y, t02m.y + t13m.x);

            float2 (*tmp)[1024] = src; src = dst; dst = tmp;
            __syncthreads();
        }
    }  // spectra in bufB

    // ---- power spectrum: P + 0i into bufA[0] ----
#pragma unroll
    for (int it = 0; it < 2; it++) {
        int k = t + it * 512;
        int m = (1024 - k) & 1023;
        float2 z  = bufB[0][swz(k)];
        float2 zm = bufB[0][swz(m)];
        float2 z2 = bufB[1][swz(k)];
        float P = 0.5f * (z.x * z.x + z.y * z.y + zm.x * zm.x + zm.y * zm.y)
                + (z2.x * z2.x + z2.y * z2.y);
        bufA[0][swz(k)] = make_float2(P, 0.0f);
    }
    __syncthreads();

    // ---- inverse (== forward on real-even P): 5 stages, 1 signal ----
    {
        float2 (*src)[1024] = bufA;
        float2 (*dst)[1024] = bufB;
#pragma unroll
        for (int s = 0; s < 5; s++) {
            if (t < 256) {
                const int L = 1 << (2 * s);
                const int q = t & (L - 1);
                const int d = ((t >> (2 * s)) << (2 * s + 2)) | q;
                const float2 w1t = tw[q << (8 - 2 * s)];
                const float2 w2t = make_float2(w1t.x * w1t.x - w1t.y * w1t.y,
                                               2.0f * w1t.x * w1t.y);
                const float2 w3t = cmul(w2t, w1t);

                float2 a0 = src[0][swz(t)];
                float2 a1 = src[0][swz(t + 256)];
                float2 a2 = src[0][swz(t + 512)];
                float2 a3 = src[0][swz(t + 768)];
                float2 b1 = cmul(a1, w1t);
                float2 b2 = cmul(a2, w2t);
                float2 b3 = cmul(a3, w3t);

                float2 t02p = make_float2(a0.x + b2.x, a0.y + b2.y);
                float2 t02m = make_float2(a0.x - b2.x, a0.y - b2.y);
                float2 t13p = make_float2(b1.x + b3.x, b1.y + b3.y);
                float2 t13m = make_float2(b1.x - b3.x, b1.y - b3.y);

                dst[0][swz(d)]         = make_float2(t02p.x + t13p.x, t02p.y + t13p.y);
                dst[0][swz(d + L)]     = make_float2(t02m.x + t13m.y, t02m.y - t13m.x);
                dst[0][swz(d + 2 * L)] = make_float2(t02p.x - t13p.x, t02p.y - t13p.y);
                dst[0][swz(d + 3 * L)] = make_float2(t02m.x - t13m.y, t02m.y + t13m.x);
            }
            float2 (*tmp)[1024] = src; src = dst; dst = tmp;
            __syncthreads();
        }
    }  // result in bufB[0]

    const float inv = 1.0f / (1024.0f * 1024.0f);
    g_c[(size_t)b * NSEQ + t]       = bufB[0][swz(t)].x * inv;
    g_c[(size_t)b * NSEQ + t + 512] = bufB[0][swz(t + 512)].x * inv;
}

// ---------------------------------------------------------------------------
// Kernel 2: fused gemm1 (tiled, full-K) + mlp23, chained by device flags.
// Grid 128 = 16 batch-tiles x 8 h-tiles, 512 threads, 1 CTA/SM (co-resident).
// Phase A: write h1 tile.  Flag.  Phase B: batch B = blockIdx.x runs mlp23.
// ---------------------------------------------------------------------------
#define CSH_PITCH 1025
#define RED_PITCH 66
#define TAIL_SMEM ((4 * CSH_PITCH + 1024 * 16 + 32 * RED_PITCH) * 8)

__global__ __launch_bounds__(512, 1)
void tail_kernel(const float* __restrict__ W1, const float* __restrict__ b1,
                 const float* __restrict__ W2, const float* __restrict__ b2,
                 const float* __restrict__ W3, const float* __restrict__ b3,
                 float* __restrict__ out) {
    extern __shared__ char dsm[];
    u64 (*csh)[CSH_PITCH] = (u64(*)[CSH_PITCH])dsm;
    u64 (*w1d)[16]        = (u64(*)[16])(dsm + 4 * CSH_PITCH * 8);
    u64 (*red)[RED_PITCH] = (u64(*)[RED_PITCH])(dsm + (4 * CSH_PITCH + 1024 * 16) * 8);

    const int t  = threadIdx.x;
    const int B  = blockIdx.x;
    const int bt = B >> 3;
    const int ht = B & 7;
    const int b0 = bt * 8;
    const int H0 = ht * 16;

    __shared__ unsigned tgt2_s;

    // ==================== phase A: gemm1 tile ====================
#pragma unroll
    for (int it = 0; it < 8; it++) {
        int idx = t + it * 512;
        int bp_ = idx >> 10, j = idx & 1023;
        csh[bp_][j] = pk2(g_c[(b0 + 2 * bp_) * NSEQ + j],
                          g_c[(b0 + 2 * bp_ + 1) * NSEQ + j]);
    }
#pragma unroll
    for (int it = 0; it < 8; it++) {
        int idx = t + it * 512;
        int j = idx >> 2, hq = idx & 3;
        float4 wv = *(const float4*)&W1[j * HID + H0 + hq * 4];
        ulonglong2* dst = (ulonglong2*)&w1d[j][hq * 4];
        dst[0] = make_ulonglong2(pk2(wv.x, wv.x), pk2(wv.y, wv.y));
        dst[1] = make_ulonglong2(pk2(wv.z, wv.z), pk2(wv.w, wv.w));
    }
    __syncthreads();

    {
        const int bp = t & 3;
        const int h4 = (t >> 2) & 3;
        const int jq = t >> 4;
        const int j0 = jq * 32;

        u64 a0 = 0ull, a1 = 0ull, a2 = 0ull, a3 = 0ull;
#pragma unroll 8
        for (int j = j0; j < j0 + 32; j++) {
            u64 cv = csh[bp][j];
            const ulonglong2* wr = (const ulonglong2*)&w1d[j][h4 * 4];
            ulonglong2 w01 = wr[0];
            ulonglong2 w23 = wr[1];
            a0 = fma2(cv, w01.x, a0);
            a1 = fma2(cv, w01.y, a1);
            a2 = fma2(cv, w23.x, a2);
            a3 = fma2(cv, w23.y, a3);
        }
        ulonglong2* rr = (ulonglong2*)&red[jq][bp * 16 + h4 * 4];
        rr[0] = make_ulonglong2(a0, a1);
        rr[1] = make_ulonglong2(a2, a3);
    }
    __syncthreads();

    if (t < 64) {
        int bp_ = t >> 4, h = t & 15;
        int cell = bp_ * 16 + h;
        u64 s0 = 0ull, s1 = 0ull, s2 = 0ull, s3 = 0ull;
#pragma unroll
        for (int q = 0; q < 32; q += 4) {
            s0 = add2(s0, red[q + 0][cell]);
            s1 = add2(s1, red[q + 1][cell]);
            s2 = add2(s2, red[q + 2][cell]);
            s3 = add2(s3, red[q + 3][cell]);
        }
        u64 s = add2(add2(s0, s1), add2(s2, s3));
        float va, vb;
        upk2(s, va, vb);
        float bb = b1[H0 + h];
        g_h1[(b0 + 2 * bp_) * HID + H0 + h]     = celu1(va + bb);
        g_h1[(b0 + 2 * bp_ + 1) * HID + H0 + h] = celu1(vb + bb);
    }

    // release: this (bt,ht) tile of h1 is ready
    __threadfence();
    __syncthreads();
    if (t == 0) {
        unsigned old = atomicAdd(&g_flag2[bt], 1);
        tgt2_s = (old & ~7u) + 8u;        // epoch base + all 8 tiles
    }
    __syncthreads();
    const unsigned tgt2 = tgt2_s;

    // acquire: wait for all 8 h-tiles of this bt-group
    if (t == 0) {
        const unsigned* fl = &g_flag2[bt];
        while ((int)(ldacq(fl) - tgt2) < 0) { }
    }
    __syncthreads();
    __threadfence();

    // ==================== phase B: mlp23 for batch B ====================
    {
        float* h1s = (float*)dsm;              // 128 floats
        float* s2  = (float*)(dsm + 512);      // 4*128 floats

        if (t < HID) h1s[t] = g_h1[(size_t)B * HID + t];
        __syncthreads();

        const int kh = t >> 7;                 // 0..3
        const int h  = t & 127;
        const int k0 = kh * 32;
        float acc0 = 0.f, acc1 = 0.f, acc2 = 0.f, acc3 = 0.f;
#pragma unroll
        for (int k = k0; k < k0 + 32; k += 4) {
            acc0 += h1s[k + 0] * W2[(k + 0) * HID + h];
            acc1 += h1s[k + 1] * W2[(k + 1) * HID + h];
            acc2 += h1s[k + 2] * W2[(k + 2) * HID + h];
            acc3 += h1s[k + 3] * W2[(k + 3) * HID + h];
        }
        s2[kh * 128 + h] = (acc0 + acc1) + (acc2 + acc3);
        __syncthreads();

        if (t < HID) {
            float v = s2[h] + s2[128 + h] + s2[256 + h] + s2[384 + h] + b2[h];
            h1s[h] = celu1(v) * W3[h];
        }
        __syncthreads();
#pragma unroll
        for (int o = 64; o > 0; o >>= 1) {
            if (t < o) h1s[t] += h1s[t + o];
            __syncthreads();
        }
        if (t == 0) out[B] = h1s[0] + b3[0];
    }
}

// ---------------------------------------------------------------------------
extern "C" void kernel_launch(void* const* d_in, const int* in_sizes, int n_in,
                              void* d_out, int out_size) {
    const float* x  = (const float*)d_in[0];
    const float* W1 = (const float*)d_in[1];
    const float* b1 = (const float*)d_in[2];
    const float* W2 = (const float*)d_in[3];
    const float* b2 = (const float*)d_in[4];
    const float* W3 = (const float*)d_in[5];
    const float* b3 = (const float*)d_in[6];
    float* out = (float*)d_out;

    cudaFuncSetAttribute(tail_kernel,
                         cudaFuncAttributeMaxDynamicSharedMemorySize, TAIL_SMEM);

    fftcorr_kernel<<<BATCH, 512>>>(x);
    tail_kernel<<<128, 512, TAIL_SMEM>>>(W1, b1, W2, b2, W3, b3, out);
}

// round 10
// speedup vs baseline: 1.1045x; 1.0037x over previous
#include <cuda_runtime.h>
#include <cuda_bf16.h>

// ---------------------------------------------------------------------------
// MLP_TI_Gram: y = MLP(mean-of-shifted-diagonal of per-batch Gram matrix)
// diag-mean == circular autocorrelation == FFT(sum_d |FFT(x_d)|^2)/N^2
// (Wiener-Khinchin; P real-even so inverse == forward FFT, real part).
// B=128, N=1024, H=128.
// Pipeline: fftcorr (radix-4, XOR-swizzled smem) -> tiled gemm1 -> mlp23.
// ---------------------------------------------------------------------------

#define BATCH 128
#define NSEQ  1024
#define HID   128

typedef unsigned long long u64;

__device__ float g_c[BATCH * NSEQ];    // correlation (scratch)
__device__ float g_h1[BATCH * HID];    // layer-1 activations (scratch)

// ---- f32x2 packed helpers (Blackwell, PTX-only) ---------------------------
__device__ __forceinline__ u64 pk2(float lo, float hi) {
    u64 r;
    asm("mov.b64 %0, {%1,%2};" : "=l"(r) : "f"(lo), "f"(hi));
    return r;
}
__device__ __forceinline__ void upk2(u64 v, float& lo, float& hi) {
    asm("mov.b64 {%0,%1}, %2;" : "=f"(lo), "=f"(hi) : "l"(v));
}
__device__ __forceinline__ u64 fma2(u64 a, u64 b, u64 c) {
    u64 d;
    asm("fma.rn.f32x2 %0, %1, %2, %3;" : "=l"(d) : "l"(a), "l"(b), "l"(c));
    return d;
}
__device__ __forceinline__ u64 add2(u64 a, u64 b) {
    u64 d;
    asm("add.rn.f32x2 %0, %1, %2;" : "=l"(d) : "l"(a), "l"(b));
    return d;
}

__device__ __forceinline__ float celu1(float v) {
    return v > 0.0f ? v : expm1f(v);
}
__device__ __forceinline__ float2 cmul(float2 a, float2 b) {
    return make_float2(a.x * b.x - a.y * b.y, a.x * b.y + a.y * b.x);
}
// XOR bank swizzle: bijection on [0,1024); keeps linear runs conflict-free and
// makes the stage-0 stride-4 scatter hit all 32 banks.
__device__ __forceinline__ int swz(int a) { return a ^ ((a >> 5) & 31); }

// ---------------------------------------------------------------------------
// Kernel 1: correlation via FFT (Wiener-Khinchin), radix-4 Stockham,
// XOR-swizzled shared memory. 128 blocks (one per batch), 512 threads.
// ---------------------------------------------------------------------------
__global__ __launch_bounds__(512, 1)
void fftcorr_kernel(const float* __restrict__ x) {
    __shared__ float2 bufA[2][1024];   // 16KB (swizzled layout)
    __shared__ float2 bufB[2][1024];   // 16KB (swizzled layout)
    __shared__ float2 tw[512];         // W_1024^m, m in [0,512)

    const int b = blockIdx.x;
    const int t = threadIdx.x;

    // twiddle: tw[m] = exp(-2*pi*i*m/1024)
    {
        float s_, c_;
        sincospif(-(float)t * (1.0f / 512.0f), &s_, &c_);
        tw[t] = make_float2(c_, s_);
    }
    // zero imag of channel-2 signal (bijection: linear covers all slots)
    bufA[1][t].y = 0.0f;
    bufA[1][t + 512].y = 0.0f;

    // load x[b]: 3072 floats = 768 float4, scatter to (j, d), swizzled
    {
        const float4* __restrict__ xv = (const float4*)(x + (size_t)b * NSEQ * 3);
        for (int i = t; i < 768; i += 512) {
            float4 v = xv[i];
            float vals[4] = {v.x, v.y, v.z, v.w};
            int e = 4 * i;
#pragma unroll
            for (int k = 0; k < 4; k++) {
                int ee = e + k;
                int j = ee / 3;
                int d = ee - 3 * j;
                int pj = swz(j);
                if (d == 0)      bufA[0][pj].x = vals[k];
                else if (d == 1) bufA[0][pj].y = vals[k];
                else             bufA[1][pj].x = vals[k];
            }
        }
    }
    __syncthreads();

    const int f = t >> 8;     // signal (0: ch0+i*ch1, 1: ch2)
    const int i = t & 255;

    // ---- forward: 5 radix-4 stages, 2 signals ----
    {
        float2 (*src)[1024] = bufA;
        float2 (*dst)[1024] = bufB;
#pragma unroll
        for (int s = 0; s < 5; s++) {
            const int L = 1 << (2 * s);
            const int q = i & (L - 1);
            const int d = ((i >> (2 * s)) << (2 * s + 2)) | q;
            const float2 w1t = tw[q << (8 - 2 * s)];
            const float2 w2t = make_float2(w1t.x * w1t.x - w1t.y * w1t.y,
                                           2.0f * w1t.x * w1t.y);
            const float2 w3t = cmul(w2t, w1t);

            float2 a0 = src[f][swz(i)];
            float2 a1 = src[f][swz(i + 256)];
            float2 a2 = src[f][swz(i + 512)];
            float2 a3 = src[f][swz(i + 768)];
            float2 b1 = cmul(a1, w1t);
            float2 b2 = cmul(a2, w2t);
            float2 b3 = cmul(a3, w3t);

            float2 t02p = make_float2(a0.x + b2.x, a0.y + b2.y);
            float2 t02m = make_float2(a0.x - b2.x, a0.y - b2.y);
            float2 t13p = make_float2(b1.x + b3.x, b1.y + b3.y);
            float2 t13m = make_float2(b1.x - b3.x, b1.y - b3.y);

            dst[f][swz(d)]         = make_float2(t02p.x + t13p.x, t02p.y + t13p.y);
            dst[f][swz(d + L)]     = make_float2(t02m.x + t13m.y, t02m.y - t13m.x);
            dst[f][swz(d + 2 * L)] = make_float2(t02p.x - t13p.x, t02p.y - t13p.y);
            dst[f][swz(d + 3 * L)] = make_float2(t02m.x - t13m.y, t02m.y + t13m.x);

            float2 (*tmp)[1024] = src; src = dst; dst = tmp;
            __syncthreads();
        }
    }  // spectra in bufB

    // ---- power spectrum: P + 0i into bufA[0] ----
#pragma unroll
    for (int it = 0; it < 2; it++) {
        int k = t + it * 512;
        int m = (1024 - k) & 1023;
        float2 z  = bufB[0][swz(k)];
        float2 zm = bufB[0][swz(m)];
        float2 z2 = bufB[1][swz(k)];
        float P = 0.5f * (z.x * z.x + z.y * z.y + zm.x * zm.x + zm.y * zm.y)
                + (z2.x * z2.x + z2.y * z2.y);
        bufA[0][swz(k)] = make_float2(P, 0.0f);
    }
    __syncthreads();

    // ---- inverse (== forward on real-even P): 5 stages, 1 signal ----
    {
        float2 (*src)[1024] = bufA;
        float2 (*dst)[1024] = bufB;
#pragma unroll
        for (int s = 0; s < 5; s++) {
            if (t < 256) {
                const int L = 1 << (2 * s);
                const int q = t & (L - 1);
                const int d = ((t >> (2 * s)) << (2 * s + 2)) | q;
                const float2 w1t = tw[q << (8 - 2 * s)];
                const float2 w2t = make_float2(w1t.x * w1t.x - w1t.y * w1t.y,
                                               2.0f * w1t.x * w1t.y);
                const float2 w3t = cmul(w2t, w1t);

                float2 a0 = src[0][swz(t)];
                float2 a1 = src[0][swz(t + 256)];
                float2 a2 = src[0][swz(t + 512)];
                float2 a3 = src[0][swz(t + 768)];
                float2 b1 = cmul(a1, w1t);
                float2 b2 = cmul(a2, w2t);
                float2 b3 = cmul(a3, w3t);

                float2 t02p = make_float2(a0.x + b2.x, a0.y + b2.y);
                float2 t02m = make_float2(a0.x - b2.x, a0.y - b2.y);
                float2 t13p = make_float2(b1.x + b3.x, b1.y + b3.y);
                float2 t13m = make_float2(b1.x - b3.x, b1.y - b3.y);

                dst[0][swz(d)]         = make_float2(t02p.x + t13p.x, t02p.y + t13p.y);
                dst[0][swz(d + L)]     = make_float2(t02m.x + t13m.y, t02m.y - t13m.x);
                dst[0][swz(d + 2 * L)] = make_float2(t02p.x - t13p.x, t02p.y - t13p.y);
                dst[0][swz(d + 3 * L)] = make_float2(t02m.x - t13m.y, t02m.y + t13m.x);
            }
            float2 (*tmp)[1024] = src; src = dst; dst = tmp;
            __syncthreads();
        }
    }  // result in bufB[0]

    const float inv = 1.0f / (1024.0f * 1024.0f);
    g_c[(size_t)b * NSEQ + t]       = bufB[0][swz(t)].x * inv;
    g_c[(size_t)b * NSEQ + t + 512] = bufB[0][swz(t + 512)].x * inv;
}

// ---------------------------------------------------------------------------
// Kernel 2: tiled layer-1 GEMM, full K per block, writes FINAL h1 (w/ celu).
// Grid 128 = 16 batch-tiles (8 batches) x 8 h-tiles (16 h). 512 threads.
// ---------------------------------------------------------------------------
#define CSH_PITCH 1025
#define RED_PITCH 66
#define GEMM1_SMEM ((4 * CSH_PITCH + 1024 * 16 + 32 * RED_PITCH) * 8)

__global__ __launch_bounds__(512, 1)
void gemm1_kernel(const float* __restrict__ W1, const float* __restrict__ b1) {
    extern __shared__ char dsm[];
    u64 (*csh)[CSH_PITCH] = (u64(*)[CSH_PITCH])dsm;
    u64 (*w1d)[16]        = (u64(*)[16])(dsm + 4 * CSH_PITCH * 8);
    u64 (*red)[RED_PITCH] = (u64(*)[RED_PITCH])(dsm + (4 * CSH_PITCH + 1024 * 16) * 8);

    const int t  = threadIdx.x;
    const int bt = blockIdx.x >> 3;
    const int ht = blockIdx.x & 7;
    const int b0 = bt * 8;
    const int H0 = ht * 16;

#pragma unroll
    for (int it = 0; it < 8; it++) {
        int idx = t + it * 512;
        int bp_ = idx >> 10, j = idx & 1023;
        csh[bp_][j] = pk2(g_c[(b0 + 2 * bp_) * NSEQ + j],
                          g_c[(b0 + 2 * bp_ + 1) * NSEQ + j]);
    }
#pragma unroll
    for (int it = 0; it < 8; it++) {
        int idx = t + it * 512;
        int j = idx >> 2, hq = idx & 3;
        float4 wv = *(const float4*)&W1[j * HID + H0 + hq * 4];
        ulonglong2* dst = (ulonglong2*)&w1d[j][hq * 4];
        dst[0] = make_ulonglong2(pk2(wv.x, wv.x), pk2(wv.y, wv.y));
        dst[1] = make_ulonglong2(pk2(wv.z, wv.z), pk2(wv.w, wv.w));
    }
    __syncthreads();

    const int bp = t & 3;
    const int h4 = (t >> 2) & 3;
    const int jq = t >> 4;
    const int j0 = jq * 32;

    u64 a0 = 0ull, a1 = 0ull, a2 = 0ull, a3 = 0ull;
#pragma unroll 8
    for (int j = j0; j < j0 + 32; j++) {
        u64 cv = csh[bp][j];
        const ulonglong2* wr = (const ulonglong2*)&w1d[j][h4 * 4];
        ulonglong2 w01 = wr[0];
        ulonglong2 w23 = wr[1];
        a0 = fma2(cv, w01.x, a0);
        a1 = fma2(cv, w01.y, a1);
        a2 = fma2(cv, w23.x, a2);
        a3 = fma2(cv, w23.y, a3);
    }
    {
        ulonglong2* rr = (ulonglong2*)&red[jq][bp * 16 + h4 * 4];
        rr[0] = make_ulonglong2(a0, a1);
        rr[1] = make_ulonglong2(a2, a3);
    }
    __syncthreads();

    if (t < 64) {
        int bp_ = t >> 4, h = t & 15;
        int cell = bp_ * 16 + h;
        u64 s0 = 0ull, s1 = 0ull, s2 = 0ull, s3 = 0ull;
#pragma unroll
        for (int q = 0; q < 32; q += 4) {
            s0 = add2(s0, red[q + 0][cell]);
            s1 = add2(s1, red[q + 1][cell]);
            s2 = add2(s2, red[q + 2][cell]);
            s3 = add2(s3, red[q + 3][cell]);
        }
        u64 s = add2(add2(s0, s1), add2(s2, s3));
        float va, vb;
        upk2(s, va, vb);
        float bb = b1[H0 + h];
        g_h1[(b0 + 2 * bp_) * HID + H0 + h]     = celu1(va + bb);
        g_h1[(b0 + 2 * bp_ + 1) * HID + H0 + h] = celu1(vb + bb);
    }
}

// ---------------------------------------------------------------------------
// Kernel 3: layers 2+3. 128 blocks (one per batch), 256 threads (k split 2).
// ---------------------------------------------------------------------------
__global__ __launch_bounds__(256, 1)
void mlp23_kernel(const float* __restrict__ W2, const float* __restrict__ b2,
                  const float* __restrict__ W3, const float* __restrict__ b3,
                  float* __restrict__ out) {
    __shared__ float h1s[HID];
    __shared__ float s2[2][HID];

    const int b = blockIdx.x, t = threadIdx.x;
    if (t < HID) h1s[t] = g_h1[b * HID + t];
    __syncthreads();

    const int kh = t >> 7, h = t & (HID - 1);
    const int k0 = kh * 64;
    float acc0 = 0.f, acc1 = 0.f, acc2 = 0.f, acc3 = 0.f;
#pragma unroll
    for (int k = k0; k < k0 + 64; k += 4) {
        acc0 += h1s[k + 0] * W2[(k + 0) * HID + h];
        acc1 += h1s[k + 1] * W2[(k + 1) * HID + h];
        acc2 += h1s[k + 2] * W2[(k + 2) * HID + h];
        acc3 += h1s[k + 3] * W2[(k + 3) * HID + h];
    }
    s2[kh][h] = (acc0 + acc1) + (acc2 + acc3);
    __syncthreads();

    if (t < HID) {
        float v = s2[0][t] + s2[1][t] + b2[t];
        s2[0][t] = celu1(v) * W3[t];
    }
    __syncthreads();
#pragma unroll
    for (int o = 64; o > 0; o >>= 1) {
        if (t < o) s2[0][t] += s2[0][t + o];
        __syncthreads();
    }
    if (t == 0) out[b] = s2[0][0] + b3[0];
}

// ---------------------------------------------------------------------------
extern "C" void kernel_launch(void* const* d_in, const int* in_sizes, int n_in,
                              void* d_out, int out_size) {
    const float* x  = (const float*)d_in[0];
    const float* W1 = (const float*)d_in[1];
    const float* b1 = (const float*)d_in[2];
    const float* W2 = (const float*)d_in[3];
    const float* b2 = (const float*)d_in[4];
    const float* W3 = (const float*)d_in[5];
    const float* b3 = (const float*)d_in[6];
    float* out = (float*)d_out;

    cudaFuncSetAttribute(gemm1_kernel,
                         cudaFuncAttributeMaxDynamicSharedMemorySize, GEMM1_SMEM);

    fftcorr_kernel<<<BATCH, 512>>>(x);
    gemm1_kernel<<<128, 512, GEMM1_SMEM>>>(W1, b1);
    mlp23_kernel<<<BATCH, 256>>>(W2, b2, W3, b3, out);
}

// round 11
// speedup vs baseline: 1.1065x; 1.0019x over previous
#include <cuda_runtime.h>
#include <cuda_bf16.h>

// ---------------------------------------------------------------------------
// MLP_TI_Gram: y = MLP(mean-of-shifted-diagonal of per-batch Gram matrix)
// diag-mean == circular autocorrelation == FFT(sum_d |FFT(x_d)|^2)/N^2
// (Wiener-Khinchin; P real-even so inverse == forward FFT, real part).
// B=128, N=1024, H=128.
// Pipeline: fftcorr -> gemm1 -> mlp23, chained with PDL so each consumer's
// launch + weight staging overlaps the producer's execution.
// ---------------------------------------------------------------------------

#define BATCH 128
#define NSEQ  1024
#define HID   128

typedef unsigned long long u64;

__device__ float g_c[BATCH * NSEQ];    // correlation (scratch)
__device__ float g_h1[BATCH * HID];    // layer-1 activations (scratch)

// ---- f32x2 packed helpers (Blackwell, PTX-only) ---------------------------
__device__ __forceinline__ u64 pk2(float lo, float hi) {
    u64 r;
    asm("mov.b64 %0, {%1,%2};" : "=l"(r) : "f"(lo), "f"(hi));
    return r;
}
__device__ __forceinline__ void upk2(u64 v, float& lo, float& hi) {
    asm("mov.b64 {%0,%1}, %2;" : "=f"(lo), "=f"(hi) : "l"(v));
}
__device__ __forceinline__ u64 fma2(u64 a, u64 b, u64 c) {
    u64 d;
    asm("fma.rn.f32x2 %0, %1, %2, %3;" : "=l"(d) : "l"(a), "l"(b), "l"(c));
    return d;
}
__device__ __forceinline__ u64 add2(u64 a, u64 b) {
    u64 d;
    asm("add.rn.f32x2 %0, %1, %2;" : "=l"(d) : "l"(a), "l"(b));
    return d;
}

__device__ __forceinline__ float celu1(float v) {
    return v > 0.0f ? v : expm1f(v);
}
__device__ __forceinline__ float2 cmul(float2 a, float2 b) {
    return make_float2(a.x * b.x - a.y * b.y, a.x * b.y + a.y * b.x);
}

// ---- PDL primitives --------------------------------------------------------
__device__ __forceinline__ void pdl_wait() {
    asm volatile("griddepcontrol.wait;" ::: "memory");
}
__device__ __forceinline__ void pdl_trigger() {
    asm volatile("griddepcontrol.launch_dependents;" ::: "memory");
}

// ---------------------------------------------------------------------------
// Kernel 1: correlation via FFT (Wiener-Khinchin), radix-4 Stockham.
// 128 blocks (one per batch), 512 threads.
// ---------------------------------------------------------------------------
__global__ __launch_bounds__(512, 1)
void fftcorr_kernel(const float* __restrict__ x) {
    __shared__ float2 bufA[2][1024];   // 16KB
    __shared__ float2 bufB[2][1024];   // 16KB
    __shared__ float2 tw[512];         // W_1024^m, m in [0,512)

    const int b = blockIdx.x;
    const int t = threadIdx.x;

    // twiddle: tw[m] = exp(-2*pi*i*m/1024)
    {
        float s_, c_;
        sincospif(-(float)t * (1.0f / 512.0f), &s_, &c_);
        tw[t] = make_float2(c_, s_);
    }
    bufA[1][t].y = 0.0f;
    bufA[1][t + 512].y = 0.0f;

    // load x[b]: 3072 floats = 768 float4, scatter to (j, d)
    {
        const float4* __restrict__ xv = (const float4*)(x + (size_t)b * NSEQ * 3);
        for (int i = t; i < 768; i += 512) {
            float4 v = xv[i];
            float vals[4] = {v.x, v.y, v.z, v.w};
            int e = 4 * i;
#pragma unroll
            for (int k = 0; k < 4; k++) {
                int ee = e + k;
                int j = ee / 3;
                int d = ee - 3 * j;
                if (d == 0)      bufA[0][j].x = vals[k];
                else if (d == 1) bufA[0][j].y = vals[k];
                else             bufA[1][j].x = vals[k];
            }
        }
    }
    __syncthreads();

    const int f = t >> 8;
    const int i = t & 255;

    // ---- forward: 5 radix-4 stages, 2 signals ----
    {
        float2 (*src)[1024] = bufA;
        float2 (*dst)[1024] = bufB;
#pragma unroll
        for (int s = 0; s < 5; s++) {
            const int L = 1 << (2 * s);
            const int q = i & (L - 1);
            const int d = ((i >> (2 * s)) << (2 * s + 2)) | q;
            const float2 w1t = tw[q << (8 - 2 * s)];
            const float2 w2t = make_float2(w1t.x * w1t.x - w1t.y * w1t.y,
                                           2.0f * w1t.x * w1t.y);
            const float2 w3t = cmul(w2t, w1t);

            float2 a0 = src[f][i];
            float2 a1 = src[f][i + 256];
            float2 a2 = src[f][i + 512];
            float2 a3 = src[f][i + 768];
            float2 b1 = cmul(a1, w1t);
            float2 b2 = cmul(a2, w2t);
            float2 b3 = cmul(a3, w3t);

            float2 t02p = make_float2(a0.x + b2.x, a0.y + b2.y);
            float2 t02m = make_float2(a0.x - b2.x, a0.y - b2.y);
            float2 t13p = make_float2(b1.x + b3.x, b1.y + b3.y);
            float2 t13m = make_float2(b1.x - b3.x, b1.y - b3.y);

            dst[f][d]         = make_float2(t02p.x + t13p.x, t02p.y + t13p.y);
            dst[f][d + L]     = make_float2(t02m.x + t13m.y, t02m.y - t13m.x);
            dst[f][d + 2 * L] = make_float2(t02p.x - t13p.x, t02p.y - t13p.y);
            dst[f][d + 3 * L] = make_float2(t02m.x - t13m.y, t02m.y + t13m.x);

            float2 (*tmp)[1024] = src; src = dst; dst = tmp;
            __syncthreads();
        }
    }  // spectra in bufB

    // ---- power spectrum: P + 0i into bufA[0] ----
#pragma unroll
    for (int it = 0; it < 2; it++) {
        int k = t + it * 512;
        int m = (1024 - k) & 1023;
        float2 z  = bufB[0][k];
        float2 zm = bufB[0][m];
        float2 z2 = bufB[1][k];
        float P = 0.5f * (z.x * z.x + z.y * z.y + zm.x * zm.x + zm.y * zm.y)
                + (z2.x * z2.x + z2.y * z2.y);
        bufA[0][k] = make_float2(P, 0.0f);
    }
    __syncthreads();

    // ---- inverse (== forward on real-even P): 5 stages, 1 signal ----
    {
        float2 (*src)[1024] = bufA;
        float2 (*dst)[1024] = bufB;
#pragma unroll
        for (int s = 0; s < 5; s++) {
            if (t < 256) {
                const int L = 1 << (2 * s);
                const int q = t & (L - 1);
                const int d = ((t >> (2 * s)) << (2 * s + 2)) | q;
                const float2 w1t = tw[q << (8 - 2 * s)];
                const float2 w2t = make_float2(w1t.x * w1t.x - w1t.y * w1t.y,
                                               2.0f * w1t.x * w1t.y);
                const float2 w3t = cmul(w2t, w1t);

                float2 a0 = src[0][t];
                float2 a1 = src[0][t + 256];
                float2 a2 = src[0][t + 512];
                float2 a3 = src[0][t + 768];
                float2 b1 = cmul(a1, w1t);
                float2 b2 = cmul(a2, w2t);
                float2 b3 = cmul(a3, w3t);

                float2 t02p = make_float2(a0.x + b2.x, a0.y + b2.y);
                float2 t02m = make_float2(a0.x - b2.x, a0.y - b2.y);
                float2 t13p = make_float2(b1.x + b3.x, b1.y + b3.y);
                float2 t13m = make_float2(b1.x - b3.x, b1.y - b3.y);

                dst[0][d]         = make_float2(t02p.x + t13p.x, t02p.y + t13p.y);
                dst[0][d + L]     = make_float2(t02m.x + t13m.y, t02m.y - t13m.x);
                dst[0][d + 2 * L] = make_float2(t02p.x - t13p.x, t02p.y - t13p.y);
                dst[0][d + 3 * L] = make_float2(t02m.x - t13m.y, t02m.y + t13m.x);
            }
            float2 (*tmp)[1024] = src; src = dst; dst = tmp;
            __syncthreads();
        }
    }  // result in bufB[0]

    const float inv = 1.0f / (1024.0f * 1024.0f);
    g_c[(size_t)b * NSEQ + t]       = bufB[0][t].x * inv;
    g_c[(size_t)b * NSEQ + t + 512] = bufB[0][t + 512].x * inv;

    __threadfence();
    pdl_trigger();    // release dependents (all g_c stores fenced)
}

// ---------------------------------------------------------------------------
// Kernel 2: tiled layer-1 GEMM (PDL consumer of fftcorr).
// W1 staged into smem BEFORE griddepcontrol.wait -> overlaps fft execution.
// Grid 128 = 16 batch-tiles (8 batches) x 8 h-tiles (16 h). 512 threads.
// ---------------------------------------------------------------------------
#define CSH_PITCH 1025
#define RED_PITCH 66
#define GEMM1_SMEM ((4 * CSH_PITCH + 1024 * 16 + 32 * RED_PITCH) * 8)

__global__ __launch_bounds__(512, 1)
void gemm1_kernel(const float* __restrict__ W1, const float* __restrict__ b1) {
    extern __shared__ char dsm[];
    u64 (*csh)[CSH_PITCH] = (u64(*)[CSH_PITCH])dsm;
    u64 (*w1d)[16]        = (u64(*)[16])(dsm + 4 * CSH_PITCH * 8);
    u64 (*red)[RED_PITCH] = (u64(*)[RED_PITCH])(dsm + (4 * CSH_PITCH + 1024 * 16) * 8);

    const int t  = threadIdx.x;
    const int bt = blockIdx.x >> 3;
    const int ht = blockIdx.x & 7;
    const int b0 = bt * 8;
    const int H0 = ht * 16;

    // ---- pre-wait prologue: stage W1 slice (independent of fft output) ----
#pragma unroll
    for (int it = 0; it < 8; it++) {
        int idx = t + it * 512;
        int j = idx >> 2, hq = idx & 3;
        float4 wv = *(const float4*)&W1[j * HID + H0 + hq * 4];
        ulonglong2* dst = (ulonglong2*)&w1d[j][hq * 4];
        dst[0] = make_ulonglong2(pk2(wv.x, wv.x), pk2(wv.y, wv.y));
        dst[1] = make_ulonglong2(pk2(wv.z, wv.z), pk2(wv.w, wv.w));
    }

    pdl_wait();   // fftcorr's g_c now visible

#pragma unroll
    for (int it = 0; it < 8; it++) {
        int idx = t + it * 512;
        int bp_ = idx >> 10, j = idx & 1023;
        csh[bp_][j] = pk2(g_c[(b0 + 2 * bp_) * NSEQ + j],
                          g_c[(b0 + 2 * bp_ + 1) * NSEQ + j]);
    }
    __syncthreads();

    const int bp = t & 3;
    const int h4 = (t >> 2) & 3;
    const int jq = t >> 4;
    const int j0 = jq * 32;

    u64 a0 = 0ull, a1 = 0ull, a2 = 0ull, a3 = 0ull;
#pragma unroll 8
    for (int j = j0; j < j0 + 32; j++) {
        u64 cv = csh[bp][j];
        const ulonglong2* wr = (const ulonglong2*)&w1d[j][h4 * 4];
        ulonglong2 w01 = wr[0];
        ulonglong2 w23 = wr[1];
        a0 = fma2(cv, w01.x, a0);
        a1 = fma2(cv, w01.y, a1);
        a2 = fma2(cv, w23.x, a2);
        a3 = fma2(cv, w23.y, a3);
    }
    {
        ulonglong2* rr = (ulonglong2*)&red[jq][bp * 16 + h4 * 4];
        rr[0] = make_ulonglong2(a0, a1);
        rr[1] = make_ulonglong2(a2, a3);
    }
    __syncthreads();

    if (t < 64) {
        int bp_ = t >> 4, h = t & 15;
        int cell = bp_ * 16 + h;
        u64 s0 = 0ull, s1 = 0ull, s2 = 0ull, s3 = 0ull;
#pragma unroll
        for (int q = 0; q < 32; q += 4) {
            s0 = add2(s0, red[q + 0][cell]);
            s1 = add2(s1, red[q + 1][cell]);
            s2 = add2(s2, red[q + 2][cell]);
            s3 = add2(s3, red[q + 3][cell]);
        }
        u64 s = add2(add2(s0, s1), add2(s2, s3));
        float va, vb;
        upk2(s, va, vb);
        float bb = b1[H0 + h];
        g_h1[(b0 + 2 * bp_) * HID + H0 + h]     = celu1(va + bb);
        g_h1[(b0 + 2 * bp_ + 1) * HID + H0 + h] = celu1(vb + bb);
        __threadfence();
    }
    __syncthreads();
    pdl_trigger();
}

// ---------------------------------------------------------------------------
// Kernel 3: layers 2+3 (PDL consumer of gemm1). W2/b2/W3 staged into smem
// BEFORE griddepcontrol.wait. 128 blocks, 256 threads.
// ---------------------------------------------------------------------------
#define MLP23_SMEM ((16384 + 128 + 128 + 512 + 128) * 4)

__global__ __launch_bounds__(256, 1)
void mlp23_kernel(const float* __restrict__ W2, const float* __restrict__ b2,
                  const float* __restrict__ W3, const float* __restrict__ b3,
                  float* __restrict__ out) {
    extern __shared__ float msm[];
    float* w2s = msm;               // [128*128]
    float* b2s = msm + 16384;       // [128]
    float* w3s = msm + 16512;       // [128]
    float* s2  = msm + 16640;       // [4][128] (only [2] used wide)
    float* h1s = msm + 17152;       // [128]

    const int b = blockIdx.x, t = threadIdx.x;

    // ---- pre-wait prologue: stage all weights ----
    {
        const float4* __restrict__ W2v = (const float4*)W2;
        float4* w2sv = (float4*)w2s;
#pragma unroll
        for (int i = 0; i < 16; i++) w2sv[t + i * 256] = W2v[t + i * 256];
        if (t < 128) {
            b2s[t] = b2[t];
            w3s[t] = W3[t];
        }
    }

    pdl_wait();   // gemm1's g_h1 now visible

    if (t < HID) h1s[t] = g_h1[b * HID + t];
    __syncthreads();

    const int kh = t >> 7, h = t & (HID - 1);
    const int k0 = kh * 64;
    float acc0 = 0.f, acc1 = 0.f, acc2 = 0.f, acc3 = 0.f;
#pragma unroll
    for (int k = k0; k < k0 + 64; k += 4) {
        acc0 += h1s[k + 0] * w2s[(k + 0) * HID + h];
        acc1 += h1s[k + 1] * w2s[(k + 1) * HID + h];
        acc2 += h1s[k + 2] * w2s[(k + 2) * HID + h];
        acc3 += h1s[k + 3] * w2s[(k + 3) * HID + h];
    }
    s2[kh * 128 + h] = (acc0 + acc1) + (acc2 + acc3);
    __syncthreads();

    if (t < HID) {
        float v = s2[t] + s2[128 + t] + b2s[t];
        s2[t] = celu1(v) * w3s[t];
    }
    __syncthreads();
#pragma unroll
    for (int o = 64; o > 0; o >>= 1) {
        if (t < o) s2[t] += s2[t + o];
        __syncthreads();
    }
    if (t == 0) out[b] = s2[0] + b3[0];
}

// ---------------------------------------------------------------------------
extern "C" void kernel_launch(void* const* d_in, const int* in_sizes, int n_in,
                              void* d_out, int out_size) {
    const float* x  = (const float*)d_in[0];
    const float* W1 = (const float*)d_in[1];
    const float* b1 = (const float*)d_in[2];
    const float* W2 = (const float*)d_in[3];
    const float* b2 = (const float*)d_in[4];
    const float* W3 = (const float*)d_in[5];
    const float* b3 = (const float*)d_in[6];
    float* out = (float*)d_out;

    static int configured = 0;
    if (!configured) {
        cudaFuncSetAttribute(gemm1_kernel,
                             cudaFuncAttributeMaxDynamicSharedMemorySize,
                             GEMM1_SMEM);
        cudaFuncSetAttribute(mlp23_kernel,
                             cudaFuncAttributeMaxDynamicSharedMemorySize,
                             MLP23_SMEM);
        configured = 1;
    }

    fftcorr_kernel<<<BATCH, 512>>>(x);

    cudaLaunchAttribute attrs[1];
    attrs[0].id = cudaLaunchAttributeProgrammaticStreamSerialization;
    attrs[0].val.programmaticStreamSerializationAllowed = 1;

    {   // gemm1 with PDL
        cudaLaunchConfig_t cfg = {};
        cfg.gridDim = dim3(128, 1, 1);
        cfg.blockDim = dim3(512, 1, 1);
        cfg.dynamicSmemBytes = GEMM1_SMEM;
        cfg.attrs = attrs;
        cfg.numAttrs = 1;
        cudaLaunchKernelEx(&cfg, gemm1_kernel, W1, b1);
    }
    {   // mlp23 with PDL
        cudaLaunchConfig_t cfg = {};
        cfg.gridDim = dim3(BATCH, 1, 1);
        cfg.blockDim = dim3(256, 1, 1);
        cfg.dynamicSmemBytes = MLP23_SMEM;
        cfg.attrs = attrs;
        cfg.numAttrs = 1;
        cudaLaunchKernelEx(&cfg, mlp23_kernel, W2, b2, W3, b3, out);
    }
}